// round 9
// baseline (speedup 1.0000x reference)
#include <cuda_runtime.h>

// XrayTransforms: standardize -> soft-hist equalize -> 2x bilinear (=2x2 avg) -> normalize
// x: (2,1,512,512) f32, out: (2,1,256,256) f32
//
// Round 9: 4 launches. k_table deleted; k_out scans the 256-bin hist per
// block (redundant, overlapped) and evaluates equalize directly per pixel
// with a branch-free padded 25-tap loop.

#define NB 256
#define HW 512
#define NPIX (HW*HW)            // 262144 per batch
#define SUBN 8192
#define SUBSCALE 8160.0f        // 255*32 sub-bins across [0,1]
#define BETA 7.5091258e-5f      // A / 8160^2, A = 5000
#define STEP32_C 0.85745500f    // exp(-2048*BETA) = exp(-2*A*Delta^2)
#define NMM 128                 // minmax blocks
#define HBLKN 74                // hist blocks per batch
#define RADIUS 12
#define TWO_A_D  39.21568627450980f   // 2*A*Delta (Delta = 1/255)
#define A_D2     0.07689350249903883f // A*Delta^2
#define RATIO_C  0.85745500f          // exp(-2*A*Delta^2)
#define INV255   (1.0f/255.0f)
#define CWIN 1120               // conv smem window (needs 1088)
#define PAD (NB + 2*RADIUS)     // 280: padded cdfn/mask arrays

__device__ float g_pmin[NMM];
__device__ float g_pmax[NMM];
__device__ float g_scale[2];            // [0]=min, [1]=1/(max-min+1e-6)
__device__ float g_mom[2][SUBN];        // fine hist (atomic-accumulated)
__device__ float g_hist[2][NB];

__global__ void k_minmax(const float* __restrict__ x) {
    __shared__ float smn[256], smx[256];
    // zero g_mom: 128 blocks x 128 elements
    if (threadIdx.x < 128)
        ((float*)g_mom)[blockIdx.x * 128 + threadIdx.x] = 0.0f;

    const float4* x4 = (const float4*)x;
    int base = blockIdx.x * 1024 + threadIdx.x;     // 131072 float4 / 128 blocks
    float mn = 1e30f, mx = -1e30f;
    #pragma unroll
    for (int q = 0; q < 4; q++) {
        float4 v = x4[base + q * 256];
        mn = fminf(mn, fminf(fminf(v.x, v.y), fminf(v.z, v.w)));
        mx = fmaxf(mx, fmaxf(fmaxf(v.x, v.y), fmaxf(v.z, v.w)));
    }
    smn[threadIdx.x] = mn; smx[threadIdx.x] = mx;
    __syncthreads();
    for (int o = 128; o; o >>= 1) {
        if (threadIdx.x < o) {
            smn[threadIdx.x] = fminf(smn[threadIdx.x], smn[threadIdx.x + o]);
            smx[threadIdx.x] = fmaxf(smx[threadIdx.x], smx[threadIdx.x + o]);
        }
        __syncthreads();
    }
    if (threadIdx.x == 0) { g_pmin[blockIdx.x] = smn[0]; g_pmax[blockIdx.x] = smx[0]; }
}

// 1 shared atomic per pixel into 8192 fine sub-bins; atomic flush to g_mom.
__global__ void k_hist(const float* __restrict__ x) {
    __shared__ float sh[SUBN];                 // 32KB
    __shared__ float smm[256];
    const int t = threadIdx.x;
    smm[t] = (t < NMM) ? g_pmin[t] : 1e30f;
    __syncthreads();
    for (int o = 128; o; o >>= 1) { if (t < o) smm[t] = fminf(smm[t], smm[t + o]); __syncthreads(); }
    const float mn = smm[0];
    __syncthreads();
    smm[t] = (t < NMM) ? g_pmax[t] : -1e30f;
    __syncthreads();
    for (int o = 128; o; o >>= 1) { if (t < o) smm[t] = fmaxf(smm[t], smm[t + o]); __syncthreads(); }
    const float inv = 1.0f / (smm[0] - mn + 1e-6f);
    if (blockIdx.x == 0 && blockIdx.y == 0 && t == 0) { g_scale[0] = mn; g_scale[1] = inv; }
    __syncthreads();

    for (int i = t; i < SUBN; i += blockDim.x) sh[i] = 0.0f;
    __syncthreads();

    const int b = blockIdx.y;
    const float4* xb = (const float4*)(x + b * NPIX);
    const int n4 = NPIX / 4;
    const int stride = gridDim.x * blockDim.x;
    for (int idx = blockIdx.x * blockDim.x + t; idx < n4; idx += stride) {
        float4 p4 = xb[idx];
        float vv[4] = {p4.x, p4.y, p4.z, p4.w};
        #pragma unroll
        for (int q = 0; q < 4; q++) {
            float v = (vv[q] - mn) * inv;
            int i = __float2int_rn(v * SUBSCALE);
            atomicAdd(&sh[i], 1.0f);
        }
    }
    __syncthreads();
    // counts are exact integers in f32 -> order-independent, deterministic
    float* dst = g_mom[b];
    for (int i = t; i < SUBN; i += blockDim.x) {
        float v = sh[i];
        if (v != 0.0f) atomicAdd(&dst[i], v);
    }
}

// Gaussian conv: smem-staged window, warp per bin, fixed 27 unrolled taps.
__global__ void k_conv() {
    __shared__ float s[CWIN];
    const int b = blockIdx.y;
    const int j0 = blockIdx.x * 8;          // 8 bins per block
    const int lo = 32 * j0 - 420;
    const int tid = threadIdx.x;            // 256 threads = 8 warps

    for (int i = tid; i < CWIN; i += 256) {
        int gi = lo + i;
        s[i] = (gi >= 0 && gi < SUBN) ? g_mom[b][gi] : 0.0f;
    }
    __syncthreads();

    const int wid = tid >> 5;
    const int lane = tid & 31;
    float fm = (float)(lane - 420);
    float w = __expf(-BETA * fm * fm);
    float r = __expf(-BETA * (64.0f * fm + 1024.0f));
    const float* p = s + 32 * wid + lane;
    float h = 0.0f;
    #pragma unroll
    for (int it = 0; it < 27; it++) {
        h += w * p[it * 32];
        w *= r;
        r *= STEP32_C;
    }
    #pragma unroll
    for (int o = 16; o; o >>= 1) h += __shfl_xor_sync(0xFFFFFFFFu, h, o);
    if (lane == 0) g_hist[b][j0 + wid] = h;
}

__device__ __forceinline__ float eq_direct(float xraw, float mn, float inv,
                                           const float* __restrict__ c_pad,
                                           const float* __restrict__ m_pad) {
    float v = (xraw - mn) * inv;
    int k = __float2int_rn(v * 255.0f);
    int jlo = k - RADIUS;
    float d0 = v - (float)jlo * INV255;
    float w = __expf(-5000.0f * d0 * d0);
    float r = __expf(TWO_A_D * d0 - A_D2);
    const float* cp = c_pad + jlo + RADIUS;   // indices 0..24 always in [0, PAD)
    const float* mp = m_pad + jlo + RADIUS;
    float num = 0.0f, den = 0.0f;
    #pragma unroll
    for (int st = 0; st < 2 * RADIUS + 1; st++) {
        num = fmaf(w, cp[st], num);
        den = fmaf(w, mp[st], den);
        w *= r;
        r *= RATIO_C;
    }
    return num / (den + 1e-10f);
}

// scan -> padded cdfn -> direct per-pixel equalize + 2x2 avg + normalize.
__global__ void k_out(const float* __restrict__ x, float* __restrict__ out) {
    __shared__ float s[NB];
    __shared__ float c_pad[PAD];
    __shared__ float m_pad[PAD];
    const int tid = threadIdx.x;            // 256 threads
    const int b = blockIdx.x >> 8;          // 512 blocks, 256 per batch

    c_pad[tid] = 0.0f; m_pad[tid] = 0.0f;
    if (tid < PAD - NB) { c_pad[NB + tid] = 0.0f; m_pad[NB + tid] = 0.0f; }
    s[tid] = g_hist[b][tid];
    __syncthreads();
    #pragma unroll
    for (int o = 1; o < NB; o <<= 1) {
        float add = (tid >= o) ? s[tid - o] : 0.0f;
        __syncthreads();
        s[tid] += add;
        __syncthreads();
    }
    {
        float total = s[NB - 1];
        float invS  = 1.0f / (total + 1e-10f);
        float cdf   = s[tid] * invS;
        float cdf0  = s[0] * invS;
        c_pad[tid + RADIUS] = (cdf - cdf0) / (1.0f - cdf0 + 1e-10f);
        m_pad[tid + RADIUS] = 1.0f;
    }
    __syncthreads();

    int idx = blockIdx.x * 256 + tid;       // 131072 output pixels
    int rem = idx & 0xFFFF;
    int oy = rem >> 8;
    int ox = rem & 255;
    const float* base = x + b * NPIX;
    float2 t0 = ((const float2*)(base + (2 * oy)     * HW))[ox];
    float2 t1 = ((const float2*)(base + (2 * oy + 1) * HW))[ox];

    const float mn  = g_scale[0];
    const float inv = g_scale[1];
    float e = eq_direct(t0.x, mn, inv, c_pad, m_pad)
            + eq_direct(t0.y, mn, inv, c_pad, m_pad)
            + eq_direct(t1.x, mn, inv, c_pad, m_pad)
            + eq_direct(t1.y, mn, inv, c_pad, m_pad);
    out[idx] = (0.25f * e - 0.15f) / 0.1f;
}

extern "C" void kernel_launch(void* const* d_in, const int* in_sizes, int n_in,
                              void* d_out, int out_size) {
    const float* x = (const float*)d_in[0];
    float* out = (float*)d_out;
    k_minmax<<<NMM, 256>>>(x);
    k_hist<<<dim3(HBLKN, 2), 256>>>(x);
    k_conv<<<dim3(32, 2), 256>>>();
    k_out<<<512, 256>>>(x, out);
}

// round 10
// speedup vs baseline: 1.0833x; 1.0833x over previous
#include <cuda_runtime.h>

// XrayTransforms: standardize -> soft-hist equalize -> 2x bilinear (=2x2 avg) -> normalize
// x: (2,1,512,512) f32, out: (2,1,256,256) f32
//
// Round 10: single persistent kernel, 128 co-resident blocks, software grid
// barriers between phases:
//   A minmax partials (+ zero g_mom)   [bar]
//   B reduce minmax; fine hist (smem, 1 atomic/px); atomic flush  [bar]
//   C Gaussian conv 4 bins/block (smem window, 27 fixed taps)     [bar]
//   D redundant scan -> cdfn; 128 eq-table entries/block          [bar]
//   E output: 2x2 avg of table lerps + normalize

#define NB 256
#define HW 512
#define NPIX (HW*HW)            // 262144 per batch
#define SUBN 8192
#define SUBSCALE 8160.0f        // 255*32 sub-bins across [0,1]
#define BETA 7.5091258e-5f      // A / 8160^2, A = 5000
#define STEP32_C 0.85745500f    // exp(-2048*BETA) = exp(-2*A*Delta^2)
#define TABN 8192
#define GRID 128
#define RADIUS 12
#define TWO_A_D  39.21568627450980f   // 2*A*Delta (Delta = 1/255)
#define A_D2     0.07689350249903883f // A*Delta^2
#define RATIO_C  0.85745500f          // exp(-2*A*Delta^2)
#define INV255   (1.0f/255.0f)
#define PAD (NB + 2*RADIUS)     // 280

__device__ float g_pmin[GRID];
__device__ float g_pmax[GRID];
__device__ float g_mom[2][SUBN];        // fine hist (atomic-accumulated)
__device__ float g_hist[2][NB];
__device__ float g_eqtab[2][TABN];

__device__ volatile int g_bar_cnt;      // zero-init; returns to 0 each barrier
__device__ volatile int g_bar_gen;      // monotonically increases (replay-safe)

__device__ __forceinline__ void gridbar() {
    __syncthreads();
    if (threadIdx.x == 0) {
        int gen = g_bar_gen;
        __threadfence();
        if (atomicAdd((int*)&g_bar_cnt, 1) == GRID - 1) {
            g_bar_cnt = 0;
            __threadfence();
            atomicExch((int*)&g_bar_gen, gen + 1);
        } else {
            while (g_bar_gen == gen) __nanosleep(64);
            __threadfence();
        }
    }
    __syncthreads();
}

__device__ __forceinline__ float eq_lerp(float xraw, float mn, float inv,
                                         const float* __restrict__ tb) {
    float v = (xraw - mn) * inv;
    float t = v * (float)(TABN - 1);
    int i0 = (int)t;
    float f = t - (float)i0;
    float e0 = __ldg(tb + i0);
    float e1 = __ldg(tb + i0 + 1);
    return fmaf(f, e1 - e0, e0);
}

__global__ void __launch_bounds__(256, 1)
k_fused(const float* __restrict__ x, float* __restrict__ out) {
    __shared__ float S[8448];            // 33KB, reused across phases
    __shared__ float s_mn, s_inv;
    const int bid = blockIdx.x;
    const int t = threadIdx.x;
    const float4* x4 = (const float4*)x;

    // ---- Phase A: zero g_mom slice + block min/max partials ----
    if (t < 128) ((float*)g_mom)[bid * 128 + t] = 0.0f;
    {
        int base = bid * 1024 + t;       // 131072 float4 total / 128 blocks
        float mn = 1e30f, mx = -1e30f;
        #pragma unroll
        for (int q = 0; q < 4; q++) {
            float4 v = x4[base + q * 256];
            mn = fminf(mn, fminf(fminf(v.x, v.y), fminf(v.z, v.w)));
            mx = fmaxf(mx, fmaxf(fmaxf(v.x, v.y), fmaxf(v.z, v.w)));
        }
        S[t] = mn; S[256 + t] = mx;      // use S[0..511] temporarily
        __syncthreads();
        for (int o = 128; o; o >>= 1) {
            if (t < o) {
                S[t] = fminf(S[t], S[t + o]);
                S[256 + t] = fmaxf(S[256 + t], S[256 + t + o]);
            }
            __syncthreads();
        }
        if (t == 0) { g_pmin[bid] = S[0]; g_pmax[bid] = S[256]; }
    }
    gridbar();

    // ---- Phase B: reduce minmax partials; fine hist; atomic flush ----
    {
        S[t] = (t < GRID) ? g_pmin[t] : 1e30f;
        __syncthreads();
        for (int o = 128; o; o >>= 1) { if (t < o) S[t] = fminf(S[t], S[t + o]); __syncthreads(); }
        if (t == 0) s_mn = S[0];
        __syncthreads();
        S[t] = (t < GRID) ? g_pmax[t] : -1e30f;
        __syncthreads();
        for (int o = 128; o; o >>= 1) { if (t < o) S[t] = fmaxf(S[t], S[t + o]); __syncthreads(); }
        if (t == 0) s_inv = 1.0f / (S[0] - s_mn + 1e-6f);
        __syncthreads();
    }
    const float mn  = s_mn;
    const float inv = s_inv;

    float* bins = S + 256;               // 8192 floats
    for (int i = t; i < SUBN; i += 256) bins[i] = 0.0f;
    __syncthreads();
    {
        const int b = bid >> 6;          // 64 blocks per batch
        const int sl = bid & 63;
        const float4* xb = x4 + b * (NPIX / 4) + sl * 1024;
        #pragma unroll
        for (int q = 0; q < 4; q++) {
            float4 p4 = xb[q * 256 + t];
            float vv[4] = {p4.x, p4.y, p4.z, p4.w};
            #pragma unroll
            for (int qq = 0; qq < 4; qq++) {
                float v = (vv[qq] - mn) * inv;
                int i = __float2int_rn(v * SUBSCALE);
                atomicAdd(&bins[i], 1.0f);
            }
        }
        __syncthreads();
        float* dst = g_mom[b];
        for (int i = t; i < SUBN; i += 256) {
            float v = bins[i];
            if (v != 0.0f) atomicAdd(&dst[i], v);   // exact integer counts
        }
    }
    gridbar();

    // ---- Phase C: Gaussian conv, 4 bins per block ----
    {
        const int b = bid >> 6;
        const int j0 = (bid & 63) * 4;   // bins j0..j0+3
        const int lo = 32 * j0 - 420;
        float* win = S;                  // 960 floats
        for (int i = t; i < 960; i += 256) {
            int gi = lo + i;
            win[i] = (gi >= 0 && gi < SUBN) ? g_mom[b][gi] : 0.0f;
        }
        __syncthreads();
        const int wid = t >> 5;
        const int lane = t & 31;
        if (wid < 4) {
            float fm = (float)(lane - 420);
            float w = __expf(-BETA * fm * fm);
            float r = __expf(-BETA * (64.0f * fm + 1024.0f));
            const float* p = win + 32 * wid + lane;
            float h = 0.0f;
            #pragma unroll
            for (int it = 0; it < 27; it++) {
                h += w * p[it * 32];
                w *= r;
                r *= STEP32_C;
            }
            #pragma unroll
            for (int o = 16; o; o >>= 1) h += __shfl_xor_sync(0xFFFFFFFFu, h, o);
            if (lane == 0) g_hist[b][j0 + wid] = h;
        }
    }
    gridbar();

    // ---- Phase D: redundant scan -> padded cdfn -> 128 table entries ----
    {
        const int b = bid >> 6;
        float* s  = S;                   // 256
        float* cp = S + 256;             // 280
        float* mp = S + 544;             // 280
        cp[t] = 0.0f; mp[t] = 0.0f;
        if (t < PAD - NB) { cp[NB + t] = 0.0f; mp[NB + t] = 0.0f; }
        s[t] = g_hist[b][t];
        __syncthreads();
        #pragma unroll
        for (int o = 1; o < NB; o <<= 1) {
            float add = (t >= o) ? s[t - o] : 0.0f;
            __syncthreads();
            s[t] += add;
            __syncthreads();
        }
        {
            float total = s[NB - 1];
            float invS  = 1.0f / (total + 1e-10f);
            float cdf   = s[t] * invS;
            float cdf0  = s[0] * invS;
            cp[t + RADIUS] = (cdf - cdf0) / (1.0f - cdf0 + 1e-10f);
            mp[t + RADIUS] = 1.0f;
        }
        __syncthreads();
        if (t < 128) {
            int p = (bid & 63) * 128 + t;            // 0..8191
            float v = (float)p * (1.0f / (float)(TABN - 1));
            int k = __float2int_rn(v * 255.0f);
            int jlo = k - RADIUS;
            float d0 = v - (float)jlo * INV255;
            float w = __expf(-5000.0f * d0 * d0);
            float r = __expf(TWO_A_D * d0 - A_D2);
            const float* cpp = cp + jlo + RADIUS;
            const float* mpp = mp + jlo + RADIUS;
            float num = 0.0f, den = 0.0f;
            #pragma unroll
            for (int st = 0; st < 2 * RADIUS + 1; st++) {
                num = fmaf(w, cpp[st], num);
                den = fmaf(w, mpp[st], den);
                w *= r;
                r *= RATIO_C;
            }
            g_eqtab[b][p] = num / (den + 1e-10f);
        }
    }
    gridbar();

    // ---- Phase E: output, 1024 px per block ----
    #pragma unroll
    for (int q = 0; q < 4; q++) {
        int idx = bid * 1024 + q * 256 + t;          // 131072 output pixels
        int b = idx >> 16;
        int rem = idx & 0xFFFF;
        int oy = rem >> 8;
        int ox = rem & 255;
        const float* base = x + b * NPIX;
        float2 t0 = ((const float2*)(base + (2 * oy)     * HW))[ox];
        float2 t1 = ((const float2*)(base + (2 * oy + 1) * HW))[ox];
        const float* tb = g_eqtab[b];
        float e = eq_lerp(t0.x, mn, inv, tb)
                + eq_lerp(t0.y, mn, inv, tb)
                + eq_lerp(t1.x, mn, inv, tb)
                + eq_lerp(t1.y, mn, inv, tb);
        out[idx] = (0.25f * e - 0.15f) / 0.1f;
    }
}

extern "C" void kernel_launch(void* const* d_in, const int* in_sizes, int n_in,
                              void* d_out, int out_size) {
    const float* x = (const float*)d_in[0];
    float* out = (float*)d_out;
    k_fused<<<GRID, 256>>>(x, out);
}